// round 8
// baseline (speedup 1.0000x reference)
#include <cuda_runtime.h>
#include <math.h>

// ---------------------------------------------------------------------------
// Problem constants (match reference)
// ---------------------------------------------------------------------------
#define BATCH 32
#define HSP 28
#define WSP 28
#define CH 384
#define TQN 785          // 1 + 28*28
#define TKN 197          // 1 + 14*14
#define NHEADS 6
#define HDIM 64
#define OHS 14
#define OWS 14
#define BN_EPS_F 1e-5f
#define SCALE_F 0.05103103630798287f   // 384^-0.5 (reference scales by DIM)

#define MQ (BATCH * TQN)   // 25120
#define MKV (BATCH * TKN)  // 6304

typedef unsigned long long u64;

// packed fp32x2 FMA (sm_103a): d = a*b + c elementwise on 2 fp32 lanes
__device__ __forceinline__ u64 ffma2(u64 a, u64 b, u64 c) {
    u64 d;
    asm("fma.rn.f32x2 %0, %1, %2, %3;" : "=l"(d) : "l"(a), "l"(b), "l"(c));
    return d;
}
__device__ __forceinline__ float2 upk(u64 v) {
    float2 f;
    asm("mov.b64 {%0, %1}, %2;" : "=f"(f.x), "=f"(f.y) : "l"(v));
    return f;
}

// ---------------------------------------------------------------------------
// Scratch (no cudaMalloc allowed -> __device__ globals)
// ---------------------------------------------------------------------------
__device__ float g_qin[BATCH * TQN * CH];
__device__ float g_kin[BATCH * TKN * CH];
__device__ float g_vin[BATCH * TKN * CH];
__device__ float g_q  [BATCH * TQN * CH];
__device__ float g_k  [BATCH * TKN * CH];
__device__ float g_v  [BATCH * TKN * CH];
__device__ float g_att[BATCH * TQN * CH];

// ---------------------------------------------------------------------------
// Depthwise 3x3 conv + BN, stride 1 (query path), float4 over channels.
// ---------------------------------------------------------------------------
#define C4 (CH / 4)   // 96

__global__ __launch_bounds__(256) void convq_kernel(
    const float* __restrict__ x, const float* __restrict__ cw,
    const float* __restrict__ gam, const float* __restrict__ bet,
    const float* __restrict__ mu, const float* __restrict__ va)
{
    int idx = blockIdx.x * 256 + threadIdx.x;
    if (idx >= BATCH * TQN * C4) return;
    int c4 = idx % C4;
    int t = (idx / C4) % TQN;
    int b = idx / (C4 * TQN);
    int c = c4 * 4;
    float4* dst = (float4*)&g_qin[(b * TQN + t) * CH + c];
    if (t == 0) {
        *dst = *(const float4*)&x[(b * TQN) * CH + c];
        return;
    }
    int p = t - 1;
    int oy = p / WSP, ox = p - oy * WSP;

    float4 gm = *(const float4*)&gam[c];
    float4 vr = *(const float4*)&va[c];
    float4 bt = *(const float4*)&bet[c];
    float4 mn = *(const float4*)&mu[c];
    float inv0 = gm.x * rsqrtf(vr.x + BN_EPS_F);
    float inv1 = gm.y * rsqrtf(vr.y + BN_EPS_F);
    float inv2 = gm.z * rsqrtf(vr.z + BN_EPS_F);
    float inv3 = gm.w * rsqrtf(vr.w + BN_EPS_F);

    float a0 = 0.f, a1 = 0.f, a2 = 0.f, a3 = 0.f;
    #pragma unroll
    for (int ky = 0; ky < 3; ky++) {
        int iy = oy + ky - 1;
        if ((unsigned)iy >= HSP) continue;
        #pragma unroll
        for (int kx = 0; kx < 3; kx++) {
            int ix = ox + kx - 1;
            if ((unsigned)ix >= WSP) continue;
            float4 xv = *(const float4*)&x[(b * TQN + 1 + iy * WSP + ix) * CH + c];
            int ko = ky * 3 + kx;
            a0 += xv.x * cw[(c + 0) * 9 + ko];
            a1 += xv.y * cw[(c + 1) * 9 + ko];
            a2 += xv.z * cw[(c + 2) * 9 + ko];
            a3 += xv.w * cw[(c + 3) * 9 + ko];
        }
    }
    float4 o;
    o.x = a0 * inv0 + (bt.x - mn.x * inv0);
    o.y = a1 * inv1 + (bt.y - mn.y * inv1);
    o.z = a2 * inv2 + (bt.z - mn.z * inv2);
    o.w = a3 * inv3 + (bt.w - mn.w * inv3);
    *dst = o;
}

// ---------------------------------------------------------------------------
// Depthwise 3x3 conv + BN, stride 2, k and v fused, float4 over channels.
// ---------------------------------------------------------------------------
__global__ __launch_bounds__(256) void convkv_kernel(
    const float* __restrict__ x, const float* __restrict__ cw,
    const float* __restrict__ gam, const float* __restrict__ bet,
    const float* __restrict__ mu, const float* __restrict__ va)
{
    int idx = blockIdx.x * 256 + threadIdx.x;
    if (idx >= BATCH * TKN * C4) return;
    int c4 = idx % C4;
    int t = (idx / C4) % TKN;
    int b = idx / (C4 * TKN);
    int c = c4 * 4;
    float4* dk = (float4*)&g_kin[(b * TKN + t) * CH + c];
    float4* dv = (float4*)&g_vin[(b * TKN + t) * CH + c];
    if (t == 0) {
        float4 cls = *(const float4*)&x[(b * TQN) * CH + c];
        *dk = cls;
        *dv = cls;
        return;
    }
    int p = t - 1;
    int oy = p / OWS, ox = p - oy * OWS;

    int ck = CH + c, cv = 2 * CH + c;
    float4 gmk = *(const float4*)&gam[ck];
    float4 vrk = *(const float4*)&va[ck];
    float4 btk = *(const float4*)&bet[ck];
    float4 mnk = *(const float4*)&mu[ck];
    float4 gmv = *(const float4*)&gam[cv];
    float4 vrv = *(const float4*)&va[cv];
    float4 btv = *(const float4*)&bet[cv];
    float4 mnv = *(const float4*)&mu[cv];
    float ik0 = gmk.x * rsqrtf(vrk.x + BN_EPS_F);
    float ik1 = gmk.y * rsqrtf(vrk.y + BN_EPS_F);
    float ik2 = gmk.z * rsqrtf(vrk.z + BN_EPS_F);
    float ik3 = gmk.w * rsqrtf(vrk.w + BN_EPS_F);
    float iv0 = gmv.x * rsqrtf(vrv.x + BN_EPS_F);
    float iv1 = gmv.y * rsqrtf(vrv.y + BN_EPS_F);
    float iv2 = gmv.z * rsqrtf(vrv.z + BN_EPS_F);
    float iv3 = gmv.w * rsqrtf(vrv.w + BN_EPS_F);

    float k0 = 0.f, k1 = 0.f, k2 = 0.f, k3 = 0.f;
    float v0 = 0.f, v1 = 0.f, v2 = 0.f, v3 = 0.f;
    #pragma unroll
    for (int ky = 0; ky < 3; ky++) {
        int iy = 2 * oy + ky - 1;
        if ((unsigned)iy >= HSP) continue;
        #pragma unroll
        for (int kx = 0; kx < 3; kx++) {
            int ix = 2 * ox + kx - 1;
            if ((unsigned)ix >= WSP) continue;
            float4 xv = *(const float4*)&x[(b * TQN + 1 + iy * WSP + ix) * CH + c];
            int ko = ky * 3 + kx;
            k0 += xv.x * cw[(ck + 0) * 9 + ko];
            k1 += xv.y * cw[(ck + 1) * 9 + ko];
            k2 += xv.z * cw[(ck + 2) * 9 + ko];
            k3 += xv.w * cw[(ck + 3) * 9 + ko];
            v0 += xv.x * cw[(cv + 0) * 9 + ko];
            v1 += xv.y * cw[(cv + 1) * 9 + ko];
            v2 += xv.z * cw[(cv + 2) * 9 + ko];
            v3 += xv.w * cw[(cv + 3) * 9 + ko];
        }
    }
    float4 ok, ov;
    ok.x = k0 * ik0 + (btk.x - mnk.x * ik0);
    ok.y = k1 * ik1 + (btk.y - mnk.y * ik1);
    ok.z = k2 * ik2 + (btk.z - mnk.z * ik2);
    ok.w = k3 * ik3 + (btk.w - mnk.w * ik3);
    ov.x = v0 * iv0 + (btv.x - mnv.x * iv0);
    ov.y = v1 * iv1 + (btv.y - mnv.y * iv1);
    ov.z = v2 * iv2 + (btv.z - mnv.z * iv2);
    ov.w = v3 * iv3 + (btv.w - mnv.w * iv3);
    *dk = ok;
    *dv = ov;
}

// ---------------------------------------------------------------------------
// fp32 GEMM via packed FFMA2: C[M,384] = A[M,384] * W[384,384]^T (+ bias).
// 128x128 tile, BK=16, 256 threads.
// Accumulators: 4 row-pairs x 8 cols of packed u64 (64 fp32 outputs).
// A pairs come free from float4 LDS (adjacent rows).
// B stored DUPLICATED in SMEM as (w,w) pairs with +4-float skew every 16
// pairs -> all LDS.128 phases verified conflict-free.
// Inner loop: 6 LDS.128 + 32 FFMA2 per k-step (38 slots / 64 MACs).
// Double-buffered, one __syncthreads per k-step (WAR/RAW proven).
// ---------------------------------------------------------------------------
#define GBM 128
#define GBN 128
#define GBK 16
#define GSTR 132          // A row stride (floats)
#define BSTRD 288         // B-dup row stride (floats): max f(127)+2=284 -> 288
#define KSTEPS (CH / GBK) // 24

struct GemmSmem {
    float As[2][GBK][GSTR];
    float Bsd[2][GBK][BSTRD];
};

__device__ __forceinline__ void gemm_body(
    const float* __restrict__ A, const float* __restrict__ W,
    const float* __restrict__ bias, float* __restrict__ Cmat,
    int M, int m0, int n0, GemmSmem& sm)
{
    int tid = threadIdx.x;
    int tx = tid % 16;
    int ty = tid / 16;

    int rowA0 = tid >> 2, kq = tid & 3;
    int rowA1 = rowA0 + 64;
    // B-dup skewed layout: pair j lives at f(j) = 2j + 4*(j>>4)
    int fb0 = 2 * rowA0 + 4 * (rowA0 >> 4);
    int fb1 = 2 * rowA1 + 4 * (rowA1 >> 4);
    int bb1 = 8 * tx + 4 * (tx >> 2);   // loads: j=4tx..4tx+3 contiguous here
    int bb2 = bb1 + 144;                // j=64+4tx..+3

    float4 pa0, pa1, pb0, pb1;

    auto load_regs = [&](int k0) {
        int m_0 = m0 + rowA0;
        int m_1 = m0 + rowA1;
        pa0 = (m_0 < M) ? *(const float4*)&A[(size_t)m_0 * CH + k0 + kq * 4]
                        : make_float4(0.f, 0.f, 0.f, 0.f);
        pa1 = (m_1 < M) ? *(const float4*)&A[(size_t)m_1 * CH + k0 + kq * 4]
                        : make_float4(0.f, 0.f, 0.f, 0.f);
        pb0 = *(const float4*)&W[(size_t)(n0 + rowA0) * CH + k0 + kq * 4];
        pb1 = *(const float4*)&W[(size_t)(n0 + rowA1) * CH + k0 + kq * 4];
    };
    auto store_smem = [&](int buf) {
        sm.As[buf][kq * 4 + 0][rowA0] = pa0.x;
        sm.As[buf][kq * 4 + 1][rowA0] = pa0.y;
        sm.As[buf][kq * 4 + 2][rowA0] = pa0.z;
        sm.As[buf][kq * 4 + 3][rowA0] = pa0.w;
        sm.As[buf][kq * 4 + 0][rowA1] = pa1.x;
        sm.As[buf][kq * 4 + 1][rowA1] = pa1.y;
        sm.As[buf][kq * 4 + 2][rowA1] = pa1.z;
        sm.As[buf][kq * 4 + 3][rowA1] = pa1.w;
        *(float2*)&sm.Bsd[buf][kq * 4 + 0][fb0] = make_float2(pb0.x, pb0.x);
        *(float2*)&sm.Bsd[buf][kq * 4 + 1][fb0] = make_float2(pb0.y, pb0.y);
        *(float2*)&sm.Bsd[buf][kq * 4 + 2][fb0] = make_float2(pb0.z, pb0.z);
        *(float2*)&sm.Bsd[buf][kq * 4 + 3][fb0] = make_float2(pb0.w, pb0.w);
        *(float2*)&sm.Bsd[buf][kq * 4 + 0][fb1] = make_float2(pb1.x, pb1.x);
        *(float2*)&sm.Bsd[buf][kq * 4 + 1][fb1] = make_float2(pb1.y, pb1.y);
        *(float2*)&sm.Bsd[buf][kq * 4 + 2][fb1] = make_float2(pb1.z, pb1.z);
        *(float2*)&sm.Bsd[buf][kq * 4 + 3][fb1] = make_float2(pb1.w, pb1.w);
    };

    u64 acc2[4][8];
    #pragma unroll
    for (int p = 0; p < 4; p++)
        #pragma unroll
        for (int j = 0; j < 8; j++) acc2[p][j] = 0ULL;

    load_regs(0);
    store_smem(0);
    __syncthreads();

    #pragma unroll
    for (int it = 0; it < KSTEPS; it++) {
        int cur = it & 1;
        if (it + 1 < KSTEPS) load_regs((it + 1) * GBK);
        #pragma unroll
        for (int kk = 0; kk < GBK; kk++) {
            ulonglong2 alo = *(const ulonglong2*)&sm.As[cur][kk][ty * 4];
            ulonglong2 ahi = *(const ulonglong2*)&sm.As[cur][kk][64 + ty * 4];
            ulonglong2 b01 = *(const ulonglong2*)&sm.Bsd[cur][kk][bb1];
            ulonglong2 b23 = *(const ulonglong2*)&sm.Bsd[cur][kk][bb1 + 4];
            ulonglong2 b45 = *(const ulonglong2*)&sm.Bsd[cur][kk][bb2];
            ulonglong2 b67 = *(const ulonglong2*)&sm.Bsd[cur][kk][bb2 + 4];
            u64 a[4]  = {alo.x, alo.y, ahi.x, ahi.y};
            u64 bx[8] = {b01.x, b01.y, b23.x, b23.y, b45.x, b45.y, b67.x, b67.y};
            #pragma unroll
            for (int p = 0; p < 4; p++)
                #pragma unroll
                for (int j = 0; j < 8; j++)
                    acc2[p][j] = ffma2(a[p], bx[j], acc2[p][j]);
        }
        if (it + 1 < KSTEPS) {
            store_smem(1 - cur);   // safe: no live readers of buf 1-cur
            __syncthreads();
        }
    }

    // Epilogue: unpack row-pairs, two float4 stores per row
    #pragma unroll
    for (int p = 0; p < 4; p++) {
        int baseRow = (p < 2) ? (ty * 4 + p * 2) : (64 + ty * 4 + (p - 2) * 2);
        float2 c[8];
        #pragma unroll
        for (int j = 0; j < 8; j++) c[j] = upk(acc2[p][j]);
        int nA = n0 + tx * 4;
        int nB = n0 + 64 + tx * 4;
        #pragma unroll
        for (int e = 0; e < 2; e++) {
            int m = m0 + baseRow + e;
            if (m >= M) continue;
            float4 vA, vB;
            if (e == 0) {
                vA = make_float4(c[0].x, c[1].x, c[2].x, c[3].x);
                vB = make_float4(c[4].x, c[5].x, c[6].x, c[7].x);
            } else {
                vA = make_float4(c[0].y, c[1].y, c[2].y, c[3].y);
                vB = make_float4(c[4].y, c[5].y, c[6].y, c[7].y);
            }
            if (bias) {
                vA.x += bias[nA + 0]; vA.y += bias[nA + 1];
                vA.z += bias[nA + 2]; vA.w += bias[nA + 3];
                vB.x += bias[nB + 0]; vB.y += bias[nB + 1];
                vB.z += bias[nB + 2]; vB.w += bias[nB + 3];
            }
            *(float4*)&Cmat[(size_t)m * CH + nA] = vA;
            *(float4*)&Cmat[(size_t)m * CH + nB] = vB;
        }
    }
}

// ---------------------------------------------------------------------------
// Fused QKV projection, exact flat grid (no dead CTAs): 891 CTAs.
// ---------------------------------------------------------------------------
#define QTILES 197
#define KVTILES 50
#define QKV_CTAS ((QTILES + 2 * KVTILES) * 3)

__global__ __launch_bounds__(256, 2) void qkv_gemm(
    const float* __restrict__ wq, const float* __restrict__ wk,
    const float* __restrict__ wv)
{
    __shared__ GemmSmem sm;
    int bid = blockIdx.x;
    int nt = bid % 3;
    int mt = bid / 3;
    const float* A; const float* W; float* C; int M; int m0;
    if (mt < QTILES) {
        A = g_qin; W = wq; C = g_q; M = MQ;  m0 = mt * GBM;
    } else if (mt < QTILES + KVTILES) {
        A = g_kin; W = wk; C = g_k; M = MKV; m0 = (mt - QTILES) * GBM;
    } else {
        A = g_vin; W = wv; C = g_v; M = MKV; m0 = (mt - QTILES - KVTILES) * GBM;
    }
    gemm_body(A, W, nullptr, C, M, m0, nt * GBN, sm);
}

__global__ __launch_bounds__(256, 2) void proj_gemm(
    const float* __restrict__ wproj, const float* __restrict__ bproj,
    float* __restrict__ out)
{
    __shared__ GemmSmem sm;
    gemm_body(g_att, wproj, bproj, out, MQ, blockIdx.y * GBM,
              blockIdx.x * GBN, sm);
}

// ---------------------------------------------------------------------------
// Fused attention: per (b, head, 64-query tile).
// SMEM: only K and V tiles (104.7 KB; big L1 carveout remains).
//  - Q read directly from gmem (__ldg, broadcast; no cross-warp reuse).
//  - ps aliases the ks buffer (K dead after QK^T; extra __syncthreads fences).
// QK^T vectorized over d (float4); PV reads P as broadcast float4 per 4-j.
// ---------------------------------------------------------------------------
#define QT 64
#define PSTR 200
#define KSTR 68

__global__ __launch_bounds__(512) void attn_kernel()
{
    extern __shared__ float smf[];
    float* ks = smf;                        // TKN * KSTR  (later reused as ps)
    float* vs = ks + TKN * KSTR;            // TKN * KSTR
    float* ps = ks;                         // alias: valid after barrier below
    int b = blockIdx.z, h = blockIdx.y;
    int qt0 = blockIdx.x * QT;
    int tid = threadIdx.x;

    for (int i = tid; i < TKN * (HDIM / 4); i += 512) {
        int j = i / (HDIM / 4);
        int d4 = i % (HDIM / 4);
        float4 kv = *(const float4*)&g_k[(b * TKN + j) * CH + h * HDIM + d4 * 4];
        float4 vv = *(const float4*)&g_v[(b * TKN + j) * CH + h * HDIM + d4 * 4];
        *(float4*)&ks[j * KSTR + d4 * 4] = kv;
        *(float4*)&vs[j * KSTR + d4 * 4] = vv;
    }
    __syncthreads();

    int tx = tid & 31;
    int ty = tid >> 5;
    int q0 = ty * 4;

    // per-warp Q row pointers (clamped; invalid rows masked at write)
    const float4* qp[4];
    #pragma unroll
    for (int q = 0; q < 4; q++) {
        int t = qt0 + q0 + q;
        int tc = (t < TQN) ? t : (TQN - 1);
        qp[q] = (const float4*)&g_q[((size_t)b * TQN + tc) * CH + h * HDIM];
    }

    // ---- scores: s[q][jj], j = tx + 32*jj, vectorized over d ----
    float s[4][7];
    #pragma unroll
    for (int q = 0; q < 4; q++)
        #pragma unroll
        for (int jj = 0; jj < 7; jj++) s[q][jj] = 0.f;

    #pragma unroll 4
    for (int d4 = 0; d4 < HDIM / 4; d4++) {
        float4 kv[7];
        #pragma unroll
        for (int jj = 0; jj < 7; jj++) {
            int j = tx + jj * 32;
            kv[jj] = (j < TKN) ? *(const float4*)&ks[j * KSTR + d4 * 4]
                               : make_float4(0.f, 0.f, 0.f, 0.f);
        }
        #pragma unroll
        for (int q = 0; q < 4; q++) {
            float4 qv = __ldg(&qp[q][d4]);
            #pragma unroll
            for (int jj = 0; jj < 7; jj++) {
                s[q][jj] += qv.x * kv[jj].x;
                s[q][jj] += qv.y * kv[jj].y;
                s[q][jj] += qv.z * kv[jj].z;
                s[q][jj] += qv.w * kv[jj].w;
            }
        }
    }

    __syncthreads();   // all warps done reading ks -> safe to reuse as ps

    // ---- softmax per query row, reduced across the warp ----
    #pragma unroll
    for (int q = 0; q < 4; q++) {
        float mx = -1e30f;
        #pragma unroll
        for (int jj = 0; jj < 7; jj++) {
            int j = tx + jj * 32;
            float sv = s[q][jj] * SCALE_F;
            s[q][jj] = sv;
            if (j < TKN) mx = fmaxf(mx, sv);
        }
        #pragma unroll
        for (int o = 16; o; o >>= 1)
            mx = fmaxf(mx, __shfl_xor_sync(0xffffffffu, mx, o));
        float sum = 0.f;
        #pragma unroll
        for (int jj = 0; jj < 7; jj++) {
            int j = tx + jj * 32;
            if (j < TKN) {
                float p = __expf(s[q][jj] - mx);
                s[q][jj] = p;
                sum += p;
            }
        }
        #pragma unroll
        for (int o = 16; o; o >>= 1)
            sum += __shfl_xor_sync(0xffffffffu, sum, o);
        float rinv = 1.f / sum;
        #pragma unroll
        for (int jj = 0; jj < 7; jj++) {
            int j = tx + jj * 32;
            if (j < TKN) ps[(q0 + q) * PSTR + j] = s[q][jj] * rinv;
        }
    }
    __syncwarp();   // ps rows for this warp's queries written only by this warp

    // ---- PV: out[q][d], d = tx and tx+32; P read as float4 per 4-j ----
    float acc[4][2];
    #pragma unroll
    for (int q = 0; q < 4; q++) { acc[q][0] = 0.f; acc[q][1] = 0.f; }

    for (int j0 = 0; j0 + 4 <= TKN; j0 += 4) {
        float4 pv[4];
        #pragma unroll
        for (int q = 0; q < 4; q++)
            pv[q] = *(const float4*)&ps[(q0 + q) * PSTR + j0];
        #pragma unroll
        for (int jj = 0; jj < 4; jj++) {
            float v0 = vs[(j0 + jj) * KSTR + tx];
            float v1 = vs[(j0 + jj) * KSTR + tx + 32];
            #pragma unroll
            for (int q = 0; q < 4; q++) {
                float p = (jj == 0) ? pv[q].x : (jj == 1) ? pv[q].y
                        : (jj == 2) ? pv[q].z : pv[q].w;
                acc[q][0] += p * v0;
                acc[q][1] += p * v1;
            }
        }
    }
    { // tail: j = 196
        int j = TKN - 1;
        float v0 = vs[j * KSTR + tx];
        float v1 = vs[j * KSTR + tx + 32];
        #pragma unroll
        for (int q = 0; q < 4; q++) {
            float p = ps[(q0 + q) * PSTR + j];
            acc[q][0] += p * v0;
            acc[q][1] += p * v1;
        }
    }

    #pragma unroll
    for (int q = 0; q < 4; q++) {
        int t = qt0 + q0 + q;
        if (t < TQN) {
            float* orow = &g_att[(b * TQN + t) * CH + h * HDIM];
            orow[tx]      = acc[q][0];
            orow[tx + 32] = acc[q][1];
        }
    }
}

// ---------------------------------------------------------------------------
// Launch
// ---------------------------------------------------------------------------
extern "C" void kernel_launch(void* const* d_in, const int* in_sizes, int n_in,
                              void* d_out, int out_size)
{
    const float* x      = (const float*)d_in[0];
    const float* conv_w = (const float*)d_in[1];
    const float* bng    = (const float*)d_in[2];
    const float* bnb    = (const float*)d_in[3];
    const float* bnm    = (const float*)d_in[4];
    const float* bnv    = (const float*)d_in[5];
    const float* w_q    = (const float*)d_in[6];
    const float* w_k    = (const float*)d_in[7];
    const float* w_v    = (const float*)d_in[8];
    const float* w_proj = (const float*)d_in[9];
    const float* b_proj = (const float*)d_in[10];
    float* out = (float*)d_out;

    // 1) conv + BN token embeddings (float4 over channels)
    int nq = BATCH * TQN * C4;
    convq_kernel<<<(nq + 255) / 256, 256>>>(x, conv_w, bng, bnb, bnm, bnv);
    int nkv = BATCH * TKN * C4;
    convkv_kernel<<<(nkv + 255) / 256, 256>>>(x, conv_w, bng, bnb, bnm, bnv);

    // 2) fused QKV projections (exact flat grid, 891 CTAs)
    qkv_gemm<<<QKV_CTAS, 256>>>(w_q, w_k, w_v);

    // 3) fused attention (SMEM = K + V only: 104.7 KB)
    size_t smem = (size_t)(2 * TKN * KSTR) * sizeof(float);
    cudaFuncSetAttribute(attn_kernel, cudaFuncAttributeMaxDynamicSharedMemorySize,
                         (int)smem);
    attn_kernel<<<dim3((TQN + QT - 1) / QT, NHEADS, BATCH), 512, smem>>>();

    // 4) output projection (+bias) straight into d_out
    dim3 gproj(CH / GBN, (MQ + GBM - 1) / GBM);
    proj_gemm<<<gproj, 256>>>(w_proj, b_proj, out);
}

// round 9
// speedup vs baseline: 1.1598x; 1.1598x over previous
#include <cuda_runtime.h>
#include <math.h>
#include <stdint.h>

// ---------------------------------------------------------------------------
// Problem constants (match reference)
// ---------------------------------------------------------------------------
#define BATCH 32
#define HSP 28
#define WSP 28
#define CH 384
#define TQN 785          // 1 + 28*28
#define TKN 197          // 1 + 14*14
#define NHEADS 6
#define HDIM 64
#define OHS 14
#define OWS 14
#define BN_EPS_F 1e-5f
#define SCALE_F 0.05103103630798287f   // 384^-0.5 (reference scales by DIM)

#define MQ (BATCH * TQN)   // 25120
#define MKV (BATCH * TKN)  // 6304

// ---------------------------------------------------------------------------
// Scratch (no cudaMalloc allowed -> __device__ globals)
// ---------------------------------------------------------------------------
__device__ float g_qin[BATCH * TQN * CH];
__device__ float g_kin[BATCH * TKN * CH];
__device__ float g_vin[BATCH * TKN * CH];
__device__ float g_q  [BATCH * TQN * CH];
__device__ float g_k  [BATCH * TKN * CH];
__device__ float g_v  [BATCH * TKN * CH];
__device__ float g_att[BATCH * TQN * CH];

// ---------------------------------------------------------------------------
// Depthwise 3x3 conv + BN, stride 1 (query path), float4 over channels.
// ---------------------------------------------------------------------------
#define C4 (CH / 4)   // 96

__global__ __launch_bounds__(256) void convq_kernel(
    const float* __restrict__ x, const float* __restrict__ cw,
    const float* __restrict__ gam, const float* __restrict__ bet,
    const float* __restrict__ mu, const float* __restrict__ va)
{
    int idx = blockIdx.x * 256 + threadIdx.x;
    if (idx >= BATCH * TQN * C4) return;
    int c4 = idx % C4;
    int t = (idx / C4) % TQN;
    int b = idx / (C4 * TQN);
    int c = c4 * 4;
    float4* dst = (float4*)&g_qin[(b * TQN + t) * CH + c];
    if (t == 0) {
        *dst = *(const float4*)&x[(b * TQN) * CH + c];
        return;
    }
    int p = t - 1;
    int oy = p / WSP, ox = p - oy * WSP;

    float4 gm = *(const float4*)&gam[c];
    float4 vr = *(const float4*)&va[c];
    float4 bt = *(const float4*)&bet[c];
    float4 mn = *(const float4*)&mu[c];
    float inv0 = gm.x * rsqrtf(vr.x + BN_EPS_F);
    float inv1 = gm.y * rsqrtf(vr.y + BN_EPS_F);
    float inv2 = gm.z * rsqrtf(vr.z + BN_EPS_F);
    float inv3 = gm.w * rsqrtf(vr.w + BN_EPS_F);

    float a0 = 0.f, a1 = 0.f, a2 = 0.f, a3 = 0.f;
    #pragma unroll
    for (int ky = 0; ky < 3; ky++) {
        int iy = oy + ky - 1;
        if ((unsigned)iy >= HSP) continue;
        #pragma unroll
        for (int kx = 0; kx < 3; kx++) {
            int ix = ox + kx - 1;
            if ((unsigned)ix >= WSP) continue;
            float4 xv = *(const float4*)&x[(b * TQN + 1 + iy * WSP + ix) * CH + c];
            int ko = ky * 3 + kx;
            a0 += xv.x * cw[(c + 0) * 9 + ko];
            a1 += xv.y * cw[(c + 1) * 9 + ko];
            a2 += xv.z * cw[(c + 2) * 9 + ko];
            a3 += xv.w * cw[(c + 3) * 9 + ko];
        }
    }
    float4 o;
    o.x = a0 * inv0 + (bt.x - mn.x * inv0);
    o.y = a1 * inv1 + (bt.y - mn.y * inv1);
    o.z = a2 * inv2 + (bt.z - mn.z * inv2);
    o.w = a3 * inv3 + (bt.w - mn.w * inv3);
    *dst = o;
}

// ---------------------------------------------------------------------------
// Depthwise 3x3 conv + BN, stride 2, k and v fused, float4 over channels.
// ---------------------------------------------------------------------------
__global__ __launch_bounds__(256) void convkv_kernel(
    const float* __restrict__ x, const float* __restrict__ cw,
    const float* __restrict__ gam, const float* __restrict__ bet,
    const float* __restrict__ mu, const float* __restrict__ va)
{
    int idx = blockIdx.x * 256 + threadIdx.x;
    if (idx >= BATCH * TKN * C4) return;
    int c4 = idx % C4;
    int t = (idx / C4) % TKN;
    int b = idx / (C4 * TKN);
    int c = c4 * 4;
    float4* dk = (float4*)&g_kin[(b * TKN + t) * CH + c];
    float4* dv = (float4*)&g_vin[(b * TKN + t) * CH + c];
    if (t == 0) {
        float4 cls = *(const float4*)&x[(b * TQN) * CH + c];
        *dk = cls;
        *dv = cls;
        return;
    }
    int p = t - 1;
    int oy = p / OWS, ox = p - oy * OWS;

    int ck = CH + c, cv = 2 * CH + c;
    float4 gmk = *(const float4*)&gam[ck];
    float4 vrk = *(const float4*)&va[ck];
    float4 btk = *(const float4*)&bet[ck];
    float4 mnk = *(const float4*)&mu[ck];
    float4 gmv = *(const float4*)&gam[cv];
    float4 vrv = *(const float4*)&va[cv];
    float4 btv = *(const float4*)&bet[cv];
    float4 mnv = *(const float4*)&mu[cv];
    float ik0 = gmk.x * rsqrtf(vrk.x + BN_EPS_F);
    float ik1 = gmk.y * rsqrtf(vrk.y + BN_EPS_F);
    float ik2 = gmk.z * rsqrtf(vrk.z + BN_EPS_F);
    float ik3 = gmk.w * rsqrtf(vrk.w + BN_EPS_F);
    float iv0 = gmv.x * rsqrtf(vrv.x + BN_EPS_F);
    float iv1 = gmv.y * rsqrtf(vrv.y + BN_EPS_F);
    float iv2 = gmv.z * rsqrtf(vrv.z + BN_EPS_F);
    float iv3 = gmv.w * rsqrtf(vrv.w + BN_EPS_F);

    float k0 = 0.f, k1 = 0.f, k2 = 0.f, k3 = 0.f;
    float v0 = 0.f, v1 = 0.f, v2 = 0.f, v3 = 0.f;
    #pragma unroll
    for (int ky = 0; ky < 3; ky++) {
        int iy = 2 * oy + ky - 1;
        if ((unsigned)iy >= HSP) continue;
        #pragma unroll
        for (int kx = 0; kx < 3; kx++) {
            int ix = 2 * ox + kx - 1;
            if ((unsigned)ix >= WSP) continue;
            float4 xv = *(const float4*)&x[(b * TQN + 1 + iy * WSP + ix) * CH + c];
            int ko = ky * 3 + kx;
            k0 += xv.x * cw[(ck + 0) * 9 + ko];
            k1 += xv.y * cw[(ck + 1) * 9 + ko];
            k2 += xv.z * cw[(ck + 2) * 9 + ko];
            k3 += xv.w * cw[(ck + 3) * 9 + ko];
            v0 += xv.x * cw[(cv + 0) * 9 + ko];
            v1 += xv.y * cw[(cv + 1) * 9 + ko];
            v2 += xv.z * cw[(cv + 2) * 9 + ko];
            v3 += xv.w * cw[(cv + 3) * 9 + ko];
        }
    }
    float4 ok, ov;
    ok.x = k0 * ik0 + (btk.x - mnk.x * ik0);
    ok.y = k1 * ik1 + (btk.y - mnk.y * ik1);
    ok.z = k2 * ik2 + (btk.z - mnk.z * ik2);
    ok.w = k3 * ik3 + (btk.w - mnk.w * ik3);
    ov.x = v0 * iv0 + (btv.x - mnv.x * iv0);
    ov.y = v1 * iv1 + (btv.y - mnv.y * iv1);
    ov.z = v2 * iv2 + (btv.z - mnv.z * iv2);
    ov.w = v3 * iv3 + (btv.w - mnv.w * iv3);
    *dk = ok;
    *dv = ov;
}

// ---------------------------------------------------------------------------
// tf32 tensor-core GEMM (3xTF32 split): C[M,384] = A[M,384]*W[384,384]^T (+b)
// CTA tile 128x128, BK=16, 256 threads = 8 warps (4 M x 2 N), warp tile 32x64.
// mma.sync.aligned.m16n8k8.row.col.f32.tf32.tf32.f32; per (frag, k-slice):
// D += Ahi*Bhi + Ahi*Blo + Alo*Bhi  (residual ~ u_tf32^2 ~ 2.4e-7).
// SMEM staging: [row][k] stride 20 (frag LDS banks (20g+q)%32 all distinct).
// hi/lo split once at staging. Double-buffered, one __syncthreads/iter.
// ---------------------------------------------------------------------------
#define GBM 128
#define GBN 128
#define GBK 16
#define RS 20                 // SMEM row stride (floats)
#define KSTEPS (CH / GBK)     // 24
#define SM_BUF (GBM * RS)     // 2560 floats per buffer per array
#define OFF_AHI 0
#define OFF_ALO (2 * SM_BUF)
#define OFF_BHI (4 * SM_BUF)
#define OFF_BLO (6 * SM_BUF)
#define GEMM_SMEM_BYTES (8 * SM_BUF * 4)   // 81920

__device__ __forceinline__ uint32_t cvt_tf32(float v) {
    uint32_t r;
    asm("cvt.rna.tf32.f32 %0, %1;" : "=r"(r) : "f"(v));
    return r;
}
__device__ __forceinline__ void split4(float4 v, float4& hi, float4& lo) {
    uint32_t hx = cvt_tf32(v.x), hy = cvt_tf32(v.y),
             hz = cvt_tf32(v.z), hw = cvt_tf32(v.w);
    hi.x = __uint_as_float(hx); hi.y = __uint_as_float(hy);
    hi.z = __uint_as_float(hz); hi.w = __uint_as_float(hw);
    lo.x = __uint_as_float(cvt_tf32(v.x - hi.x));
    lo.y = __uint_as_float(cvt_tf32(v.y - hi.y));
    lo.z = __uint_as_float(cvt_tf32(v.z - hi.z));
    lo.w = __uint_as_float(cvt_tf32(v.w - hi.w));
}
__device__ __forceinline__ void mma_tf32(float* c, const uint32_t* a,
                                         uint32_t b0, uint32_t b1) {
    asm volatile(
        "mma.sync.aligned.m16n8k8.row.col.f32.tf32.tf32.f32 "
        "{%0,%1,%2,%3}, {%4,%5,%6,%7}, {%8,%9}, {%0,%1,%2,%3};"
        : "+f"(c[0]), "+f"(c[1]), "+f"(c[2]), "+f"(c[3])
        : "r"(a[0]), "r"(a[1]), "r"(a[2]), "r"(a[3]), "r"(b0), "r"(b1));
}

__device__ __forceinline__ void gemm_body(
    const float* __restrict__ A, const float* __restrict__ W,
    const float* __restrict__ bias, float* __restrict__ Cmat,
    int M, int m0, int n0, float* smf)
{
    int tid = threadIdx.x;
    int lane = tid & 31;
    int warpid = tid >> 5;
    int warp_m = warpid & 3;       // 0..3  -> m offset 32*warp_m
    int warp_n = warpid >> 2;      // 0..1  -> n offset 64*warp_n
    int g = lane >> 2;             // groupID 0..7
    int q = lane & 3;              // thread in group 0..3
    int mbase = warp_m * 32;
    int nbase = warp_n * 64;

    // staging indices: thread covers rows r0 and r0+64, k-quad q
    int r0 = tid >> 2;
    int kb = q * 4;

    float4 pa0, pa1, pb0, pb1;
    auto load_regs = [&](int k0) {
        int m_0 = m0 + r0, m_1 = m0 + r0 + 64;
        pa0 = (m_0 < M) ? *(const float4*)&A[(size_t)m_0 * CH + k0 + kb]
                        : make_float4(0.f, 0.f, 0.f, 0.f);
        pa1 = (m_1 < M) ? *(const float4*)&A[(size_t)m_1 * CH + k0 + kb]
                        : make_float4(0.f, 0.f, 0.f, 0.f);
        pb0 = *(const float4*)&W[(size_t)(n0 + r0) * CH + k0 + kb];
        pb1 = *(const float4*)&W[(size_t)(n0 + r0 + 64) * CH + k0 + kb];
    };
    auto store_smem = [&](int buf) {
        float4 hi, lo;
        int boff = buf * SM_BUF;
        split4(pa0, hi, lo);
        *(float4*)&smf[OFF_AHI + boff + r0 * RS + kb] = hi;
        *(float4*)&smf[OFF_ALO + boff + r0 * RS + kb] = lo;
        split4(pa1, hi, lo);
        *(float4*)&smf[OFF_AHI + boff + (r0 + 64) * RS + kb] = hi;
        *(float4*)&smf[OFF_ALO + boff + (r0 + 64) * RS + kb] = lo;
        split4(pb0, hi, lo);
        *(float4*)&smf[OFF_BHI + boff + r0 * RS + kb] = hi;
        *(float4*)&smf[OFF_BLO + boff + r0 * RS + kb] = lo;
        split4(pb1, hi, lo);
        *(float4*)&smf[OFF_BHI + boff + (r0 + 64) * RS + kb] = hi;
        *(float4*)&smf[OFF_BLO + boff + (r0 + 64) * RS + kb] = lo;
    };

    float acc[2][8][4];
    #pragma unroll
    for (int f = 0; f < 2; f++)
        #pragma unroll
        for (int n = 0; n < 8; n++)
            #pragma unroll
            for (int e = 0; e < 4; e++) acc[f][n][e] = 0.f;

    load_regs(0);
    store_smem(0);
    __syncthreads();

    for (int it = 0; it < KSTEPS; it++) {
        int cur = it & 1;
        if (it + 1 < KSTEPS) load_regs((it + 1) * GBK);
        int boff = cur * SM_BUF;
        const uint32_t* sAhi = (const uint32_t*)&smf[OFF_AHI + boff];
        const uint32_t* sAlo = (const uint32_t*)&smf[OFF_ALO + boff];
        const uint32_t* sBhi = (const uint32_t*)&smf[OFF_BHI + boff];
        const uint32_t* sBlo = (const uint32_t*)&smf[OFF_BLO + boff];

        #pragma unroll
        for (int kk = 0; kk < 2; kk++) {
            int kof = kk * 8;
            uint32_t ahi[2][4], alo[2][4];
            #pragma unroll
            for (int f = 0; f < 2; f++) {
                int ra = (mbase + f * 16 + g) * RS + kof + q;
                int rb = (mbase + f * 16 + g + 8) * RS + kof + q;
                ahi[f][0] = sAhi[ra];
                ahi[f][1] = sAhi[rb];
                ahi[f][2] = sAhi[ra + 4];
                ahi[f][3] = sAhi[rb + 4];
                alo[f][0] = sAlo[ra];
                alo[f][1] = sAlo[rb];
                alo[f][2] = sAlo[ra + 4];
                alo[f][3] = sAlo[rb + 4];
            }
            #pragma unroll
            for (int n = 0; n < 8; n++) {
                int rn = (nbase + n * 8 + g) * RS + kof + q;
                uint32_t bh0 = sBhi[rn], bh1 = sBhi[rn + 4];
                uint32_t bl0 = sBlo[rn], bl1 = sBlo[rn + 4];
                #pragma unroll
                for (int f = 0; f < 2; f++) {
                    mma_tf32(acc[f][n], ahi[f], bh0, bh1);
                    mma_tf32(acc[f][n], ahi[f], bl0, bl1);
                    mma_tf32(acc[f][n], alo[f], bh0, bh1);
                }
            }
        }
        if (it + 1 < KSTEPS) {
            store_smem(1 - cur);   // safe: no live readers of buf 1-cur
            __syncthreads();
        }
    }

    // Epilogue: D frag (f,n): c0=(g, 2q), c1=(g, 2q+1), c2=(g+8, 2q), c3=...
    #pragma unroll
    for (int f = 0; f < 2; f++) {
        int mr0 = m0 + mbase + f * 16 + g;
        int mr1 = mr0 + 8;
        #pragma unroll
        for (int n = 0; n < 8; n++) {
            int col = n0 + nbase + n * 8 + q * 2;
            float b0v = bias ? bias[col]     : 0.f;
            float b1v = bias ? bias[col + 1] : 0.f;
            if (mr0 < M) {
                float2 v = make_float2(acc[f][n][0] + b0v, acc[f][n][1] + b1v);
                *(float2*)&Cmat[(size_t)mr0 * CH + col] = v;
            }
            if (mr1 < M) {
                float2 v = make_float2(acc[f][n][2] + b0v, acc[f][n][3] + b1v);
                *(float2*)&Cmat[(size_t)mr1 * CH + col] = v;
            }
        }
    }
}

// ---------------------------------------------------------------------------
// Fused QKV projection, exact flat grid (no dead CTAs): 891 CTAs.
// ---------------------------------------------------------------------------
#define QTILES 197
#define KVTILES 50
#define QKV_CTAS ((QTILES + 2 * KVTILES) * 3)

__global__ __launch_bounds__(256) void qkv_gemm(
    const float* __restrict__ wq, const float* __restrict__ wk,
    const float* __restrict__ wv)
{
    extern __shared__ float smf[];
    int bid = blockIdx.x;
    int nt = bid % 3;
    int mt = bid / 3;
    const float* A; const float* W; float* C; int M; int m0;
    if (mt < QTILES) {
        A = g_qin; W = wq; C = g_q; M = MQ;  m0 = mt * GBM;
    } else if (mt < QTILES + KVTILES) {
        A = g_kin; W = wk; C = g_k; M = MKV; m0 = (mt - QTILES) * GBM;
    } else {
        A = g_vin; W = wv; C = g_v; M = MKV; m0 = (mt - QTILES - KVTILES) * GBM;
    }
    gemm_body(A, W, nullptr, C, M, m0, nt * GBN, smf);
}

__global__ __launch_bounds__(256) void proj_gemm(
    const float* __restrict__ wproj, const float* __restrict__ bproj,
    float* __restrict__ out)
{
    extern __shared__ float smf[];
    gemm_body(g_att, wproj, bproj, out, MQ, blockIdx.y * GBM,
              blockIdx.x * GBN, smf);
}

// ---------------------------------------------------------------------------
// Fused attention: per (b, head, 64-query tile). (unchanged from R8: 331.6us)
// SMEM: only K and V tiles (104.7 KB); Q via __ldg; ps aliases dead ks.
// ---------------------------------------------------------------------------
#define QT 64
#define PSTR 200
#define KSTR 68

__global__ __launch_bounds__(512) void attn_kernel()
{
    extern __shared__ float smf[];
    float* ks = smf;                        // TKN * KSTR  (later reused as ps)
    float* vs = ks + TKN * KSTR;            // TKN * KSTR
    float* ps = ks;                         // alias: valid after barrier below
    int b = blockIdx.z, h = blockIdx.y;
    int qt0 = blockIdx.x * QT;
    int tid = threadIdx.x;

    for (int i = tid; i < TKN * (HDIM / 4); i += 512) {
        int j = i / (HDIM / 4);
        int d4 = i % (HDIM / 4);
        float4 kv = *(const float4*)&g_k[(b * TKN + j) * CH + h * HDIM + d4 * 4];
        float4 vv = *(const float4*)&g_v[(b * TKN + j) * CH + h * HDIM + d4 * 4];
        *(float4*)&ks[j * KSTR + d4 * 4] = kv;
        *(float4*)&vs[j * KSTR + d4 * 4] = vv;
    }
    __syncthreads();

    int tx = tid & 31;
    int ty = tid >> 5;
    int q0 = ty * 4;

    const float4* qp[4];
    #pragma unroll
    for (int q = 0; q < 4; q++) {
        int t = qt0 + q0 + q;
        int tc = (t < TQN) ? t : (TQN - 1);
        qp[q] = (const float4*)&g_q[((size_t)b * TQN + tc) * CH + h * HDIM];
    }

    float s[4][7];
    #pragma unroll
    for (int q = 0; q < 4; q++)
        #pragma unroll
        for (int jj = 0; jj < 7; jj++) s[q][jj] = 0.f;

    #pragma unroll 4
    for (int d4 = 0; d4 < HDIM / 4; d4++) {
        float4 kv[7];
        #pragma unroll
        for (int jj = 0; jj < 7; jj++) {
            int j = tx + jj * 32;
            kv[jj] = (j < TKN) ? *(const float4*)&ks[j * KSTR + d4 * 4]
                               : make_float4(0.f, 0.f, 0.f, 0.f);
        }
        #pragma unroll
        for (int q = 0; q < 4; q++) {
            float4 qv = __ldg(&qp[q][d4]);
            #pragma unroll
            for (int jj = 0; jj < 7; jj++) {
                s[q][jj] += qv.x * kv[jj].x;
                s[q][jj] += qv.y * kv[jj].y;
                s[q][jj] += qv.z * kv[jj].z;
                s[q][jj] += qv.w * kv[jj].w;
            }
        }
    }

    __syncthreads();   // all warps done reading ks -> safe to reuse as ps

    #pragma unroll
    for (int q = 0; q < 4; q++) {
        float mx = -1e30f;
        #pragma unroll
        for (int jj = 0; jj < 7; jj++) {
            int j = tx + jj * 32;
            float sv = s[q][jj] * SCALE_F;
            s[q][jj] = sv;
            if (j < TKN) mx = fmaxf(mx, sv);
        }
        #pragma unroll
        for (int o = 16; o; o >>= 1)
            mx = fmaxf(mx, __shfl_xor_sync(0xffffffffu, mx, o));
        float sum = 0.f;
        #pragma unroll
        for (int jj = 0; jj < 7; jj++) {
            int j = tx + jj * 32;
            if (j < TKN) {
                float p = __expf(s[q][jj] - mx);
                s[q][jj] = p;
                sum += p;
            }
        }
        #pragma unroll
        for (int o = 16; o; o >>= 1)
            sum += __shfl_xor_sync(0xffffffffu, sum, o);
        float rinv = 1.f / sum;
        #pragma unroll
        for (int jj = 0; jj < 7; jj++) {
            int j = tx + jj * 32;
            if (j < TKN) ps[(q0 + q) * PSTR + j] = s[q][jj] * rinv;
        }
    }
    __syncwarp();

    float acc[4][2];
    #pragma unroll
    for (int q = 0; q < 4; q++) { acc[q][0] = 0.f; acc[q][1] = 0.f; }

    for (int j0 = 0; j0 + 4 <= TKN; j0 += 4) {
        float4 pv[4];
        #pragma unroll
        for (int q = 0; q < 4; q++)
            pv[q] = *(const float4*)&ps[(q0 + q) * PSTR + j0];
        #pragma unroll
        for (int jj = 0; jj < 4; jj++) {
            float v0 = vs[(j0 + jj) * KSTR + tx];
            float v1 = vs[(j0 + jj) * KSTR + tx + 32];
            #pragma unroll
            for (int q = 0; q < 4; q++) {
                float p = (jj == 0) ? pv[q].x : (jj == 1) ? pv[q].y
                        : (jj == 2) ? pv[q].z : pv[q].w;
                acc[q][0] += p * v0;
                acc[q][1] += p * v1;
            }
        }
    }
    {
        int j = TKN - 1;
        float v0 = vs[j * KSTR + tx];
        float v1 = vs[j * KSTR + tx + 32];
        #pragma unroll
        for (int q = 0; q < 4; q++) {
            float p = ps[(q0 + q) * PSTR + j];
            acc[q][0] += p * v0;
            acc[q][1] += p * v1;
        }
    }

    #pragma unroll
    for (int q = 0; q < 4; q++) {
        int t = qt0 + q0 + q;
        if (t < TQN) {
            float* orow = &g_att[(b * TQN + t) * CH + h * HDIM];
            orow[tx]      = acc[q][0];
            orow[tx + 32] = acc[q][1];
        }
    }
}

// ---------------------------------------------------------------------------
// Launch
// ---------------------------------------------------------------------------
extern "C" void kernel_launch(void* const* d_in, const int* in_sizes, int n_in,
                              void* d_out, int out_size)
{
    const float* x      = (const float*)d_in[0];
    const float* conv_w = (const float*)d_in[1];
    const float* bng    = (const float*)d_in[2];
    const float* bnb    = (const float*)d_in[3];
    const float* bnm    = (const float*)d_in[4];
    const float* bnv    = (const float*)d_in[5];
    const float* w_q    = (const float*)d_in[6];
    const float* w_k    = (const float*)d_in[7];
    const float* w_v    = (const float*)d_in[8];
    const float* w_proj = (const float*)d_in[9];
    const float* b_proj = (const float*)d_in[10];
    float* out = (float*)d_out;

    // 1) conv + BN token embeddings (float4 over channels)
    int nq = BATCH * TQN * C4;
    convq_kernel<<<(nq + 255) / 256, 256>>>(x, conv_w, bng, bnb, bnm, bnv);
    int nkv = BATCH * TKN * C4;
    convkv_kernel<<<(nkv + 255) / 256, 256>>>(x, conv_w, bng, bnb, bnm, bnv);

    // 2) fused QKV projections via tf32 tensor cores
    cudaFuncSetAttribute(qkv_gemm, cudaFuncAttributeMaxDynamicSharedMemorySize,
                         GEMM_SMEM_BYTES);
    qkv_gemm<<<QKV_CTAS, 256, GEMM_SMEM_BYTES>>>(w_q, w_k, w_v);

    // 3) fused attention (SMEM = K + V only: 104.7 KB)
    size_t smem = (size_t)(2 * TKN * KSTR) * sizeof(float);
    cudaFuncSetAttribute(attn_kernel, cudaFuncAttributeMaxDynamicSharedMemorySize,
                         (int)smem);
    attn_kernel<<<dim3((TQN + QT - 1) / QT, NHEADS, BATCH), 512, smem>>>();

    // 4) output projection (+bias) straight into d_out
    cudaFuncSetAttribute(proj_gemm, cudaFuncAttributeMaxDynamicSharedMemorySize,
                         GEMM_SMEM_BYTES);
    dim3 gproj(CH / GBN, (MQ + GBM - 1) / GBM);
    proj_gemm<<<gproj, 256, GEMM_SMEM_BYTES>>>(w_proj, b_proj, out);
}